// round 2
// baseline (speedup 1.0000x reference)
#include <cuda_runtime.h>
#include <cuda_bf16.h>

// RelaxedProd: B=32, N=128, D=4096, shared_errors = 128 = N1 = N2.
// s == N1 == N2 collapses all zero-padding, and the two moveaxis transposes
// cancel, so everything is elementwise / n-reduced in native (B,N,D) layout:
//   out_lin[b,n,d] = ch*ce2 + ch2*ce1
//   prod_sum[b,d]  = sum_n ce1*ce2      (head correction)
//   abs_prod[b,d]  = sum_n |ce1*ce2|
//   abs_sum[b,d]   = sum_n |ce1|
//   new_head       = ch*ch2 + 0.5*prod_sum
//   qe             = abs_sum^2 - 0.5*abs_prod
//   out_adv[b,n,d] = qe * adv
//
// Round-2 design: pure HBM-bound streamer (~321 MB). Maximize bytes in
// flight: float4 (LDG.128/STG.128) + 8-way n-split per column with a smem
// combine. 1024 blocks x 256 threads; block tile = 32 float4-columns x 8
// n-chunks of 16 rows.

#define RP_B 32
#define RP_N 128
#define RP_D 4096
#define RP_D4 (RP_D / 4)            // 1024 float4 per row
#define COLS 32                     // float4 columns per block
#define CHUNKS 8
#define NPC (RP_N / CHUNKS)         // 16 rows per chunk

__global__ __launch_bounds__(256, 6)
void relaxed_prod_kernel(const float4* __restrict__ ch,
                         const float4* __restrict__ ce1,
                         const float4* __restrict__ ch2,
                         const float4* __restrict__ ce2,
                         const float4* __restrict__ adv,
                         float4* __restrict__ out_head,
                         float4* __restrict__ out_err) {
    __shared__ float4 s_ps[CHUNKS * COLS];   // prod_sum partials
    __shared__ float4 s_ap[CHUNKS * COLS];   // abs_prod partials
    __shared__ float4 s_as[CHUNKS * COLS];   // abs_sum partials
    __shared__ float4 s_qe[COLS];            // quadr_error per column

    const int tid   = threadIdx.x;
    const int col   = tid & (COLS - 1);      // float4 column within block
    const int chunk = tid >> 5;              // n-chunk 0..7
    const int c     = blockIdx.x * COLS + col;  // global float4 column
    const int b     = c >> 10;               // c / RP_D4
    const int n0    = chunk * NPC;

    const long long ibase = ((long long)b * RP_N + n0) * RP_D4 + (c & (RP_D4 - 1));
    const long long obase = ((long long)b * 2 * RP_N + n0) * RP_D4 + (c & (RP_D4 - 1));

    const float4 h1 = ch[c];
    const float4 h2 = ch2[c];

    float4 ps = make_float4(0.f, 0.f, 0.f, 0.f);
    float4 ap = make_float4(0.f, 0.f, 0.f, 0.f);
    float4 as = make_float4(0.f, 0.f, 0.f, 0.f);

    // Pass 1: lin-err output + three partial reductions over this chunk's rows.
    #pragma unroll 4
    for (int i = 0; i < NPC; ++i) {
        const float4 a = ce1[ibase + (long long)i * RP_D4];
        const float4 e = ce2[ibase + (long long)i * RP_D4];
        float4 o;
        o.x = h1.x * e.x + h2.x * a.x;
        o.y = h1.y * e.y + h2.y * a.y;
        o.z = h1.z * e.z + h2.z * a.z;
        o.w = h1.w * e.w + h2.w * a.w;
        out_err[obase + (long long)i * RP_D4] = o;
        const float px = a.x * e.x, py = a.y * e.y, pz = a.z * e.z, pw = a.w * e.w;
        ps.x += px;        ps.y += py;        ps.z += pz;        ps.w += pw;
        ap.x += fabsf(px); ap.y += fabsf(py); ap.z += fabsf(pz); ap.w += fabsf(pw);
        as.x += fabsf(a.x); as.y += fabsf(a.y); as.z += fabsf(a.z); as.w += fabsf(a.w);
    }

    s_ps[tid] = ps;
    s_ap[tid] = ap;
    s_as[tid] = as;
    __syncthreads();

    // Threads of chunk 0 combine the 8 partials per column, emit head + qe.
    if (chunk == 0) {
        float4 tps = s_ps[col], tap = s_ap[col], tas = s_as[col];
        #pragma unroll
        for (int k = 1; k < CHUNKS; ++k) {
            const float4 p = s_ps[k * COLS + col];
            const float4 q = s_ap[k * COLS + col];
            const float4 r = s_as[k * COLS + col];
            tps.x += p.x; tps.y += p.y; tps.z += p.z; tps.w += p.w;
            tap.x += q.x; tap.y += q.y; tap.z += q.z; tap.w += q.w;
            tas.x += r.x; tas.y += r.y; tas.z += r.z; tas.w += r.w;
        }
        float4 hd, qe;
        hd.x = h1.x * h2.x + 0.5f * tps.x;
        hd.y = h1.y * h2.y + 0.5f * tps.y;
        hd.z = h1.z * h2.z + 0.5f * tps.z;
        hd.w = h1.w * h2.w + 0.5f * tps.w;
        out_head[c] = hd;
        qe.x = tas.x * tas.x - 0.5f * tap.x;
        qe.y = tas.y * tas.y - 0.5f * tap.y;
        qe.z = tas.z * tas.z - 0.5f * tap.z;
        qe.w = tas.w * tas.w - 0.5f * tap.w;
        s_qe[col] = qe;
    }
    __syncthreads();

    const float4 qe = s_qe[col];

    // Pass 2: stream adv scaled by qe into the second half of new_errors.
    const long long obase2 = obase + (long long)RP_N * RP_D4;
    #pragma unroll 4
    for (int i = 0; i < NPC; ++i) {
        const float4 v = adv[ibase + (long long)i * RP_D4];
        float4 o;
        o.x = qe.x * v.x;
        o.y = qe.y * v.y;
        o.z = qe.z * v.z;
        o.w = qe.w * v.w;
        out_err[obase2 + (long long)i * RP_D4] = o;
    }
}

extern "C" void kernel_launch(void* const* d_in, const int* in_sizes, int n_in,
                              void* d_out, int out_size) {
    const float4* ch  = (const float4*)d_in[0];   // curr_head     (B, D)
    const float4* ce1 = (const float4*)d_in[1];   // curr_errors   (B, N, D)
    const float4* ch2 = (const float4*)d_in[2];   // curr_head_2   (B, D)
    const float4* ce2 = (const float4*)d_in[3];   // curr_errors_2 (B, N, D)
    const float4* adv = (const float4*)d_in[4];   // adv_errors    (B, N, D)
    // d_in[5] = shared_errors (== N; padding collapses — unused at runtime)

    float4* out_head = (float4*)d_out;                          // B*D floats
    float4* out_err  = (float4*)((float*)d_out + RP_B * RP_D);  // B*2N*D floats

    const int total_cols = RP_B * RP_D4;          // 32768 float4 columns
    const int blocks = total_cols / COLS;         // 1024 blocks
    relaxed_prod_kernel<<<blocks, 256>>>(ch, ce1, ch2, ce2, adv,
                                         out_head, out_err);
}

// round 3
// speedup vs baseline: 1.1641x; 1.1641x over previous
#include <cuda_runtime.h>
#include <cuda_bf16.h>

// RelaxedProd: B=32, N=128, D=4096, shared_errors = 128 = N1 = N2.
// s == N1 == N2 collapses all zero-padding and the moveaxis transposes
// cancel, so everything is elementwise / n-reduced in native (B,N,D) layout:
//   out_lin[b,n,d] = ch*ce2 + ch2*ce1
//   prod_sum[b,d]  = sum_n ce1*ce2
//   abs_prod[b,d]  = sum_n |ce1*ce2|
//   abs_sum[b,d]   = sum_n |ce1|
//   new_head       = ch*ch2 + 0.5*prod_sum
//   qe             = abs_sum^2 - 0.5*abs_prod
//   out_adv[b,n,d] = qe * adv
//
// R3 design: R1 skeleton (one thread per scalar (b,d) column, no barriers —
// it beat the float4+smem variant) with the two identified fixes:
//  * 64-reg budget + explicit batch-load of 16 values per unroll chunk
//    (MLP_eff ~16 instead of reg-starved ~8)
//  * __ldcs / __stcs streaming hints (zero reuse -> evict-first, stop
//    read/write L2 churn)

#define RP_B 32
#define RP_N 128
#define RP_D 4096
#define UNR 8

__global__ __launch_bounds__(256, 4)
void relaxed_prod_kernel(const float* __restrict__ ch,
                         const float* __restrict__ ce1,
                         const float* __restrict__ ch2,
                         const float* __restrict__ ce2,
                         const float* __restrict__ adv,
                         float* __restrict__ out_head,
                         float* __restrict__ out_err) {
    const int t = blockIdx.x * blockDim.x + threadIdx.x;   // 0 .. B*D-1
    const int b = t >> 12;          // t / D
    const int d = t & (RP_D - 1);   // t % D

    const long long base  = (long long)b * RP_N * RP_D + d;
    const long long obase = (long long)b * 2 * RP_N * RP_D + d;

    const float h1 = ch[t];
    const float h2 = ch2[t];

    float prod_sum = 0.0f;
    float abs_prod = 0.0f;
    float abs_sum  = 0.0f;

    // Pass 1: lin-err output + three reductions, 16 loads batched per chunk.
    #pragma unroll 2
    for (int n0 = 0; n0 < RP_N; n0 += UNR) {
        float a[UNR], e[UNR];
        const long long off = base + (long long)n0 * RP_D;
        #pragma unroll
        for (int i = 0; i < UNR; ++i) {
            a[i] = __ldcs(ce1 + off + (long long)i * RP_D);
            e[i] = __ldcs(ce2 + off + (long long)i * RP_D);
        }
        const long long ooff = obase + (long long)n0 * RP_D;
        #pragma unroll
        for (int i = 0; i < UNR; ++i) {
            __stcs(out_err + ooff + (long long)i * RP_D, h1 * e[i] + h2 * a[i]);
            const float p = a[i] * e[i];
            prod_sum += p;
            abs_prod += fabsf(p);
            abs_sum  += fabsf(a[i]);
        }
    }

    out_head[t] = h1 * h2 + 0.5f * prod_sum;
    const float qe = abs_sum * abs_sum - 0.5f * abs_prod;

    // Pass 2: stream adv scaled by qe into the second half of new_errors.
    const long long obase2 = obase + (long long)RP_N * RP_D;
    #pragma unroll 2
    for (int n0 = 0; n0 < RP_N; n0 += UNR) {
        float v[UNR];
        const long long off = base + (long long)n0 * RP_D;
        #pragma unroll
        for (int i = 0; i < UNR; ++i)
            v[i] = __ldcs(adv + off + (long long)i * RP_D);
        const long long ooff = obase2 + (long long)n0 * RP_D;
        #pragma unroll
        for (int i = 0; i < UNR; ++i)
            __stcs(out_err + ooff + (long long)i * RP_D, qe * v[i]);
    }
}

extern "C" void kernel_launch(void* const* d_in, const int* in_sizes, int n_in,
                              void* d_out, int out_size) {
    const float* ch  = (const float*)d_in[0];   // curr_head     (B, D)
    const float* ce1 = (const float*)d_in[1];   // curr_errors   (B, N, D)
    const float* ch2 = (const float*)d_in[2];   // curr_head_2   (B, D)
    const float* ce2 = (const float*)d_in[3];   // curr_errors_2 (B, N, D)
    const float* adv = (const float*)d_in[4];   // adv_errors    (B, N, D)
    // d_in[5] = shared_errors (== N; padding collapses — unused at runtime)

    float* out_head = (float*)d_out;                 // B*D elements
    float* out_err  = (float*)d_out + RP_B * RP_D;   // B*2N*D elements

    const int total   = RP_B * RP_D;     // 131072 columns
    const int threads = 256;
    const int blocks  = total / threads; // 512
    relaxed_prod_kernel<<<blocks, threads>>>(ch, ce1, ch2, ce2, adv,
                                             out_head, out_err);
}